// round 4
// baseline (speedup 1.0000x reference)
#include <cuda_runtime.h>

#define N_NODES 100000
#define D_IN    256
#define D_H     128
#define C_CLS   40

// ---- scratch (static __device__ globals; no allocation in kernel_launch) ----
__device__ int   g_deg[N_NODES];
__device__ float g_dinv[N_NODES];
__device__ float g_A[(size_t)N_NODES * D_H];   // y (messages, pre-scaled by dinv[row])
__device__ float g_B[(size_t)N_NODES * D_H];   // agg (initialized to y, scatter target)
__device__ float g_clsn[C_CLS * D_H];          // normalized class embeddings

// ---------------------------------------------------------------------------
__global__ void k_deg_init() {
    int i = blockIdx.x * blockDim.x + threadIdx.x;
    if (i < N_NODES) g_deg[i] = 1;   // self-loop
}

__global__ void k_deg_count(const int* __restrict__ col, int E) {
    int e = blockIdx.x * blockDim.x + threadIdx.x;
    if (e < E) atomicAdd(&g_deg[col[e]], 1);
}

__global__ void k_dinv() {
    int i = blockIdx.x * blockDim.x + threadIdx.x;
    if (i < N_NODES) g_dinv[i] = rsqrtf((float)g_deg[i]);
}

// ---------------------------------------------------------------------------
// GEMM1: A[i][c] = B[i][c] = dinv[i] * sum_k x[i][k] * W1[k][c]
// block: 128 threads, 32 rows. warp w owns rows w*8..w*8+7, lane owns 4 cols.
__global__ void k_gemm1(const float* __restrict__ x, const float* __restrict__ W1) {
    __shared__ float4 xs4[32 * 64];          // 32 rows x 256 cols
    const int t = threadIdx.x;
    const int row0 = blockIdx.x * 32;
    const float4* xv = (const float4*)x;
    for (int idx = t; idx < 32 * 64; idx += 128)
        xs4[idx] = xv[(size_t)row0 * 64 + idx];
    __syncthreads();

    const int lane = t & 31;
    const int w = t >> 5;
    float acc[8][4];
#pragma unroll
    for (int r = 0; r < 8; r++) { acc[r][0]=0.f; acc[r][1]=0.f; acc[r][2]=0.f; acc[r][3]=0.f; }

    const float4* W1v = (const float4*)W1;   // [256][32] float4
    for (int k = 0; k < D_IN; k += 4) {
        float4 w0 = W1v[(k + 0) * 32 + lane];
        float4 w1 = W1v[(k + 1) * 32 + lane];
        float4 w2 = W1v[(k + 2) * 32 + lane];
        float4 w3 = W1v[(k + 3) * 32 + lane];
#pragma unroll
        for (int r = 0; r < 8; r++) {
            float4 xq = xs4[(w * 8 + r) * 64 + (k >> 2)];
            acc[r][0] = fmaf(xq.x, w0.x, fmaf(xq.y, w1.x, fmaf(xq.z, w2.x, fmaf(xq.w, w3.x, acc[r][0]))));
            acc[r][1] = fmaf(xq.x, w0.y, fmaf(xq.y, w1.y, fmaf(xq.z, w2.y, fmaf(xq.w, w3.y, acc[r][1]))));
            acc[r][2] = fmaf(xq.x, w0.z, fmaf(xq.y, w1.z, fmaf(xq.z, w2.z, fmaf(xq.w, w3.z, acc[r][2]))));
            acc[r][3] = fmaf(xq.x, w0.w, fmaf(xq.y, w1.w, fmaf(xq.z, w2.w, fmaf(xq.w, w3.w, acc[r][3]))));
        }
    }

#pragma unroll
    for (int r = 0; r < 8; r++) {
        int row = row0 + w * 8 + r;
        float s = g_dinv[row];
        float4 o = make_float4(acc[r][0]*s, acc[r][1]*s, acc[r][2]*s, acc[r][3]*s);
        ((float4*)g_A)[(size_t)row * 32 + lane] = o;
        ((float4*)g_B)[(size_t)row * 32 + lane] = o;
    }
}

// ---------------------------------------------------------------------------
// Scatter: for each edge, agg(B)[col] += y(A)[row]. Warp per edge.
// Plain scalar atomicAdd (no return value -> RED.E.ADD.F32), 4 per lane.
__global__ void k_scatter(const int* __restrict__ row,
                          const int* __restrict__ col, int E) {
    int e = (int)((blockIdx.x * (long long)blockDim.x + threadIdx.x) >> 5);
    int lane = threadIdx.x & 31;
    if (e >= E) return;
    int r = row[e];
    int c = col[e];
    float4 v = ((const float4*)g_A)[(size_t)r * 32 + lane];
    float* p = g_B + (size_t)c * D_H + lane * 4;
    atomicAdd(p + 0, v.x);
    atomicAdd(p + 1, v.y);
    atomicAdd(p + 2, v.z);
    atomicAdd(p + 3, v.w);
}

// ---------------------------------------------------------------------------
// GEMM2: h[i][k] = relu(dinv[i]*B[i][k] + b1[k]);
//        A[i][c] = B[i][c] = dinv[i] * sum_k h[i][k]*W2[k][c]
// (block reads its own rows of B into smem before overwriting them)
__global__ void k_gemm2(const float* __restrict__ W2, const float* __restrict__ b1) {
    __shared__ float4 hs4[32 * 32];          // 32 rows x 128 cols
    __shared__ float  sdinv[32];
    __shared__ float4 sb1[32];
    const int t = threadIdx.x;
    const int row0 = blockIdx.x * 32;
    if (t < 32) { sdinv[t] = g_dinv[row0 + t]; sb1[t] = ((const float4*)b1)[t]; }
    __syncthreads();

    for (int idx = t; idx < 32 * 32; idx += 128) {
        int rr = idx >> 5, cc = idx & 31;
        float4 v = ((const float4*)g_B)[(size_t)row0 * 32 + idx];
        float s = sdinv[rr];
        float4 bb = sb1[cc];
        float4 h;
        h.x = fmaxf(fmaf(s, v.x, bb.x), 0.f);
        h.y = fmaxf(fmaf(s, v.y, bb.y), 0.f);
        h.z = fmaxf(fmaf(s, v.z, bb.z), 0.f);
        h.w = fmaxf(fmaf(s, v.w, bb.w), 0.f);
        hs4[idx] = h;
    }
    __syncthreads();

    const int lane = t & 31;
    const int w = t >> 5;
    float acc[8][4];
#pragma unroll
    for (int r = 0; r < 8; r++) { acc[r][0]=0.f; acc[r][1]=0.f; acc[r][2]=0.f; acc[r][3]=0.f; }

    const float4* W2v = (const float4*)W2;   // [128][32] float4
    for (int k = 0; k < D_H; k += 4) {
        float4 w0 = W2v[(k + 0) * 32 + lane];
        float4 w1 = W2v[(k + 1) * 32 + lane];
        float4 w2 = W2v[(k + 2) * 32 + lane];
        float4 w3 = W2v[(k + 3) * 32 + lane];
#pragma unroll
        for (int r = 0; r < 8; r++) {
            float4 xq = hs4[(w * 8 + r) * 32 + (k >> 2)];
            acc[r][0] = fmaf(xq.x, w0.x, fmaf(xq.y, w1.x, fmaf(xq.z, w2.x, fmaf(xq.w, w3.x, acc[r][0]))));
            acc[r][1] = fmaf(xq.x, w0.y, fmaf(xq.y, w1.y, fmaf(xq.z, w2.y, fmaf(xq.w, w3.y, acc[r][1]))));
            acc[r][2] = fmaf(xq.x, w0.z, fmaf(xq.y, w1.z, fmaf(xq.z, w2.z, fmaf(xq.w, w3.z, acc[r][2]))));
            acc[r][3] = fmaf(xq.x, w0.w, fmaf(xq.y, w1.w, fmaf(xq.z, w2.w, fmaf(xq.w, w3.w, acc[r][3]))));
        }
    }

#pragma unroll
    for (int r = 0; r < 8; r++) {
        int row = row0 + w * 8 + r;
        float s = sdinv[w * 8 + r];
        float4 o = make_float4(acc[r][0]*s, acc[r][1]*s, acc[r][2]*s, acc[r][3]*s);
        ((float4*)g_A)[(size_t)row * 32 + lane] = o;
        ((float4*)g_B)[(size_t)row * 32 + lane] = o;
    }
}

// ---------------------------------------------------------------------------
__global__ void k_clsnorm(const float* __restrict__ cls) {
    int c = blockIdx.x, t = threadIdx.x;     // 128 threads
    float v = cls[c * D_H + t];
    float s = v * v;
#pragma unroll
    for (int o = 16; o; o >>= 1) s += __shfl_xor_sync(0xffffffffu, s, o);
    __shared__ float ws[4];
    if ((t & 31) == 0) ws[t >> 5] = s;
    __syncthreads();
    float tot = ws[0] + ws[1] + ws[2] + ws[3];
    float inv = 1.f / fmaxf(sqrtf(tot), 1e-8f);
    g_clsn[c * D_H + t] = v * inv;
}

// Final: h2[i] = dinv[i]*B[i] + b2; out[i][c] = (h2 . clsn[c]) / max(||h2||,1e-8)
__global__ void k_final(const float* __restrict__ b2, float* __restrict__ out) {
    __shared__ float4 scls[C_CLS * 32];
    __shared__ float4 sb2[32];
    const int t = threadIdx.x;
    for (int idx = t; idx < C_CLS * 32; idx += 128)
        scls[idx] = ((const float4*)g_clsn)[idx];
    if (t < 32) sb2[t] = ((const float4*)b2)[t];
    __syncthreads();

    int i = blockIdx.x * 128 + t;
    if (i >= N_NODES) return;
    float acc[C_CLS];
#pragma unroll
    for (int c = 0; c < C_CLS; c++) acc[c] = 0.f;
    float sumsq = 0.f;
    float s = g_dinv[i];
    const float4* Bp = (const float4*)g_B;
    for (int kq = 0; kq < 32; kq++) {
        float4 v = Bp[(size_t)i * 32 + kq];
        float4 bb = sb2[kq];
        float4 h;
        h.x = fmaf(s, v.x, bb.x);
        h.y = fmaf(s, v.y, bb.y);
        h.z = fmaf(s, v.z, bb.z);
        h.w = fmaf(s, v.w, bb.w);
        sumsq += h.x*h.x + h.y*h.y + h.z*h.z + h.w*h.w;
#pragma unroll
        for (int c = 0; c < C_CLS; c++) {
            float4 cv = scls[c * 32 + kq];
            acc[c] = fmaf(h.x, cv.x, fmaf(h.y, cv.y, fmaf(h.z, cv.z, fmaf(h.w, cv.w, acc[c]))));
        }
    }
    float inv = 1.f / fmaxf(sqrtf(sumsq), 1e-8f);
#pragma unroll
    for (int c = 0; c < C_CLS; c++)
        out[(size_t)i * C_CLS + c] = acc[c] * inv;
}

// ---------------------------------------------------------------------------
extern "C" void kernel_launch(void* const* d_in, const int* in_sizes, int n_in,
                              void* d_out, int out_size) {
    const float* x   = (const float*)d_in[0];
    const int*   ei  = (const int*)d_in[1];     // int32! (JAX x64 disabled)
    const float* W1  = (const float*)d_in[2];
    const float* b1  = (const float*)d_in[3];
    const float* W2  = (const float*)d_in[4];
    const float* b2  = (const float*)d_in[5];
    const float* cls = (const float*)d_in[6];
    float* out = (float*)d_out;

    const int E = in_sizes[1] / 2;
    const int* erow = ei;
    const int* ecol = ei + E;

    k_deg_init<<<(N_NODES + 255) / 256, 256>>>();
    k_deg_count<<<(E + 255) / 256, 256>>>(ecol, E);
    k_dinv<<<(N_NODES + 255) / 256, 256>>>();
    k_clsnorm<<<C_CLS, 128>>>(cls);

    k_gemm1<<<N_NODES / 32, 128>>>(x, W1);
    k_scatter<<<(E + 7) / 8, 256>>>(erow, ecol, E);   // layer-1 aggregate: B += A[row]
    k_gemm2<<<N_NODES / 32, 128>>>(W2, b1);
    k_scatter<<<(E + 7) / 8, 256>>>(erow, ecol, E);   // layer-2 aggregate
    k_final<<<(N_NODES + 127) / 128, 128>>>(b2, out);
}

// round 5
// speedup vs baseline: 2.4410x; 2.4410x over previous
#include <cuda_runtime.h>

#define N_NODES 100000
#define E_MAX   1600000
#define D_IN    256
#define D_H     128
#define C_CLS   40
#define NB_SCAN ((N_NODES + 511) / 512)   // 196

// ---- scratch ----
__device__ int   g_cnt[N_NODES];            // in-degree (w/o self loop)
__device__ int   g_start[N_NODES];          // CSR offsets
__device__ int   g_head[N_NODES];           // bucket cursors
__device__ int   g_partial[NB_SCAN];
__device__ int   g_csr_src[E_MAX];          // source node per CSR slot
__device__ float g_dinv[N_NODES];
__device__ float g_A[(size_t)N_NODES * D_H];   // y = dinv * (x@W)
__device__ float g_B[(size_t)N_NODES * D_H];   // aggregated: y[j] + sum y[src]
__device__ float g_clsn[C_CLS * D_H];

// ---------------------------------------------------------------------------
__global__ void k_cnt_init() {
    int i = blockIdx.x * blockDim.x + threadIdx.x;
    if (i < N_NODES) g_cnt[i] = 0;
}

__global__ void k_deg_count(const int* __restrict__ col, int E) {
    int e = blockIdx.x * blockDim.x + threadIdx.x;
    if (e < E) atomicAdd(&g_cnt[col[e]], 1);
}

__global__ void k_dinv() {
    int i = blockIdx.x * blockDim.x + threadIdx.x;
    if (i < N_NODES) g_dinv[i] = rsqrtf((float)(g_cnt[i] + 1));
}

// ---- two-level exclusive scan of g_cnt -> g_start (and g_head copy) ----
__global__ void k_scan1() {                  // per-block sums
    __shared__ int s[512];
    int i = blockIdx.x * 512 + threadIdx.x;
    s[threadIdx.x] = (i < N_NODES) ? g_cnt[i] : 0;
    __syncthreads();
    for (int off = 256; off > 0; off >>= 1) {
        if (threadIdx.x < off) s[threadIdx.x] += s[threadIdx.x + off];
        __syncthreads();
    }
    if (threadIdx.x == 0) g_partial[blockIdx.x] = s[0];
}

__global__ void k_scan2() {                  // single block scans NB_SCAN partials
    __shared__ int s[256];
    int t = threadIdx.x;
    s[t] = (t < NB_SCAN) ? g_partial[t] : 0;
    __syncthreads();
    for (int off = 1; off < 256; off <<= 1) {
        int v = (t >= off) ? s[t - off] : 0;
        __syncthreads();
        s[t] += v;
        __syncthreads();
    }
    if (t < NB_SCAN) g_partial[t] = s[t] - ((t < NB_SCAN) ? g_partial[t] : 0); // exclusive
}

__global__ void k_scan3() {                  // block-local exclusive scan + offset
    __shared__ int s[512];
    int t = threadIdx.x;
    int i = blockIdx.x * 512 + t;
    int own = (i < N_NODES) ? g_cnt[i] : 0;
    s[t] = own;
    __syncthreads();
    for (int off = 1; off < 512; off <<= 1) {
        int v = (t >= off) ? s[t - off] : 0;
        __syncthreads();
        s[t] += v;
        __syncthreads();
    }
    if (i < N_NODES) {
        int st = s[t] - own + g_partial[blockIdx.x];
        g_start[i] = st;
        g_head[i]  = st;
    }
}

__global__ void k_bucket(const int* __restrict__ row, const int* __restrict__ col, int E) {
    int e = blockIdx.x * blockDim.x + threadIdx.x;
    if (e < E) {
        int pos = atomicAdd(&g_head[col[e]], 1);
        g_csr_src[pos] = row[e];
    }
}

// ---------------------------------------------------------------------------
// GEMM1: A[i][c] = dinv[i] * sum_k x[i][k] * W1[k][c]
__global__ void k_gemm1(const float* __restrict__ x, const float* __restrict__ W1) {
    __shared__ float4 xs4[32 * 64];
    const int t = threadIdx.x;
    const int row0 = blockIdx.x * 32;
    const float4* xv = (const float4*)x;
    for (int idx = t; idx < 32 * 64; idx += 128)
        xs4[idx] = xv[(size_t)row0 * 64 + idx];
    __syncthreads();

    const int lane = t & 31;
    const int w = t >> 5;
    float acc[8][4];
#pragma unroll
    for (int r = 0; r < 8; r++) { acc[r][0]=0.f; acc[r][1]=0.f; acc[r][2]=0.f; acc[r][3]=0.f; }

    const float4* W1v = (const float4*)W1;
    for (int k = 0; k < D_IN; k += 4) {
        float4 w0 = W1v[(k + 0) * 32 + lane];
        float4 w1 = W1v[(k + 1) * 32 + lane];
        float4 w2 = W1v[(k + 2) * 32 + lane];
        float4 w3 = W1v[(k + 3) * 32 + lane];
#pragma unroll
        for (int r = 0; r < 8; r++) {
            float4 xq = xs4[(w * 8 + r) * 64 + (k >> 2)];
            acc[r][0] = fmaf(xq.x, w0.x, fmaf(xq.y, w1.x, fmaf(xq.z, w2.x, fmaf(xq.w, w3.x, acc[r][0]))));
            acc[r][1] = fmaf(xq.x, w0.y, fmaf(xq.y, w1.y, fmaf(xq.z, w2.y, fmaf(xq.w, w3.y, acc[r][1]))));
            acc[r][2] = fmaf(xq.x, w0.z, fmaf(xq.y, w1.z, fmaf(xq.z, w2.z, fmaf(xq.w, w3.z, acc[r][2]))));
            acc[r][3] = fmaf(xq.x, w0.w, fmaf(xq.y, w1.w, fmaf(xq.z, w2.w, fmaf(xq.w, w3.w, acc[r][3]))));
        }
    }

#pragma unroll
    for (int r = 0; r < 8; r++) {
        int row = row0 + w * 8 + r;
        float s = g_dinv[row];
        ((float4*)g_A)[(size_t)row * 32 + lane] =
            make_float4(acc[r][0]*s, acc[r][1]*s, acc[r][2]*s, acc[r][3]*s);
    }
}

// ---------------------------------------------------------------------------
// Aggregate (CSR gather): B[j] = A[j] + sum_{src in csr[j]} A[src]. Warp/node.
__global__ void k_aggregate() {
    int node = (int)((blockIdx.x * (long long)blockDim.x + threadIdx.x) >> 5);
    int lane = threadIdx.x & 31;
    if (node >= N_NODES) return;
    const float4* Av = (const float4*)g_A;
    float4 a = Av[(size_t)node * 32 + lane];      // self term
    float acc0 = a.x, acc1 = a.y, acc2 = a.z, acc3 = a.w;
    int s = g_start[node];
    int c = g_cnt[node];
    int k = 0;
    for (; k + 4 <= c; k += 4) {
        int s0 = g_csr_src[s + k + 0];
        int s1 = g_csr_src[s + k + 1];
        int s2 = g_csr_src[s + k + 2];
        int s3 = g_csr_src[s + k + 3];
        float4 v0 = Av[(size_t)s0 * 32 + lane];
        float4 v1 = Av[(size_t)s1 * 32 + lane];
        float4 v2 = Av[(size_t)s2 * 32 + lane];
        float4 v3 = Av[(size_t)s3 * 32 + lane];
        acc0 += v0.x + v1.x + v2.x + v3.x;
        acc1 += v0.y + v1.y + v2.y + v3.y;
        acc2 += v0.z + v1.z + v2.z + v3.z;
        acc3 += v0.w + v1.w + v2.w + v3.w;
    }
    for (; k < c; k++) {
        int s0 = g_csr_src[s + k];
        float4 v0 = Av[(size_t)s0 * 32 + lane];
        acc0 += v0.x; acc1 += v0.y; acc2 += v0.z; acc3 += v0.w;
    }
    ((float4*)g_B)[(size_t)node * 32 + lane] = make_float4(acc0, acc1, acc2, acc3);
}

// ---------------------------------------------------------------------------
// GEMM2: h[i][k] = relu(dinv[i]*B[i][k] + b1[k]); A[i][c] = dinv[i]*(h@W2)[i][c]
__global__ void k_gemm2(const float* __restrict__ W2, const float* __restrict__ b1) {
    __shared__ float4 hs4[32 * 32];
    __shared__ float  sdinv[32];
    __shared__ float4 sb1[32];
    const int t = threadIdx.x;
    const int row0 = blockIdx.x * 32;
    if (t < 32) { sdinv[t] = g_dinv[row0 + t]; sb1[t] = ((const float4*)b1)[t]; }
    __syncthreads();

    for (int idx = t; idx < 32 * 32; idx += 128) {
        int rr = idx >> 5, cc = idx & 31;
        float4 v = ((const float4*)g_B)[(size_t)row0 * 32 + idx];
        float s = sdinv[rr];
        float4 bb = sb1[cc];
        float4 h;
        h.x = fmaxf(fmaf(s, v.x, bb.x), 0.f);
        h.y = fmaxf(fmaf(s, v.y, bb.y), 0.f);
        h.z = fmaxf(fmaf(s, v.z, bb.z), 0.f);
        h.w = fmaxf(fmaf(s, v.w, bb.w), 0.f);
        hs4[idx] = h;
    }
    __syncthreads();

    const int lane = t & 31;
    const int w = t >> 5;
    float acc[8][4];
#pragma unroll
    for (int r = 0; r < 8; r++) { acc[r][0]=0.f; acc[r][1]=0.f; acc[r][2]=0.f; acc[r][3]=0.f; }

    const float4* W2v = (const float4*)W2;
    for (int k = 0; k < D_H; k += 4) {
        float4 w0 = W2v[(k + 0) * 32 + lane];
        float4 w1 = W2v[(k + 1) * 32 + lane];
        float4 w2 = W2v[(k + 2) * 32 + lane];
        float4 w3 = W2v[(k + 3) * 32 + lane];
#pragma unroll
        for (int r = 0; r < 8; r++) {
            float4 xq = hs4[(w * 8 + r) * 32 + (k >> 2)];
            acc[r][0] = fmaf(xq.x, w0.x, fmaf(xq.y, w1.x, fmaf(xq.z, w2.x, fmaf(xq.w, w3.x, acc[r][0]))));
            acc[r][1] = fmaf(xq.x, w0.y, fmaf(xq.y, w1.y, fmaf(xq.z, w2.y, fmaf(xq.w, w3.y, acc[r][1]))));
            acc[r][2] = fmaf(xq.x, w0.z, fmaf(xq.y, w1.z, fmaf(xq.z, w2.z, fmaf(xq.w, w3.z, acc[r][2]))));
            acc[r][3] = fmaf(xq.x, w0.w, fmaf(xq.y, w1.w, fmaf(xq.z, w2.w, fmaf(xq.w, w3.w, acc[r][3]))));
        }
    }

#pragma unroll
    for (int r = 0; r < 8; r++) {
        int row = row0 + w * 8 + r;
        float s = sdinv[w * 8 + r];
        ((float4*)g_A)[(size_t)row * 32 + lane] =
            make_float4(acc[r][0]*s, acc[r][1]*s, acc[r][2]*s, acc[r][3]*s);
    }
}

// ---------------------------------------------------------------------------
__global__ void k_clsnorm(const float* __restrict__ cls) {
    int c = blockIdx.x, t = threadIdx.x;
    float v = cls[c * D_H + t];
    float s = v * v;
#pragma unroll
    for (int o = 16; o; o >>= 1) s += __shfl_xor_sync(0xffffffffu, s, o);
    __shared__ float ws[4];
    if ((t & 31) == 0) ws[t >> 5] = s;
    __syncthreads();
    float tot = ws[0] + ws[1] + ws[2] + ws[3];
    float inv = 1.f / fmaxf(sqrtf(tot), 1e-8f);
    g_clsn[c * D_H + t] = v * inv;
}

// Final: h2[i] = dinv[i]*B[i] + b2; out[i][c] = (h2 . clsn[c]) / max(||h2||,1e-8)
__global__ void k_final(const float* __restrict__ b2, float* __restrict__ out) {
    __shared__ float4 scls[C_CLS * 32];
    __shared__ float4 sb2[32];
    const int t = threadIdx.x;
    for (int idx = t; idx < C_CLS * 32; idx += 128)
        scls[idx] = ((const float4*)g_clsn)[idx];
    if (t < 32) sb2[t] = ((const float4*)b2)[t];
    __syncthreads();

    int i = blockIdx.x * 128 + t;
    if (i >= N_NODES) return;
    float acc[C_CLS];
#pragma unroll
    for (int c = 0; c < C_CLS; c++) acc[c] = 0.f;
    float sumsq = 0.f;
    float s = g_dinv[i];
    const float4* Bp = (const float4*)g_B;
    for (int kq = 0; kq < 32; kq++) {
        float4 v = Bp[(size_t)i * 32 + kq];
        float4 bb = sb2[kq];
        float4 h;
        h.x = fmaf(s, v.x, bb.x);
        h.y = fmaf(s, v.y, bb.y);
        h.z = fmaf(s, v.z, bb.z);
        h.w = fmaf(s, v.w, bb.w);
        sumsq += h.x*h.x + h.y*h.y + h.z*h.z + h.w*h.w;
#pragma unroll
        for (int c = 0; c < C_CLS; c++) {
            float4 cv = scls[c * 32 + kq];
            acc[c] = fmaf(h.x, cv.x, fmaf(h.y, cv.y, fmaf(h.z, cv.z, fmaf(h.w, cv.w, acc[c]))));
        }
    }
    float inv = 1.f / fmaxf(sqrtf(sumsq), 1e-8f);
#pragma unroll
    for (int c = 0; c < C_CLS; c++)
        out[(size_t)i * C_CLS + c] = acc[c] * inv;
}

// ---------------------------------------------------------------------------
extern "C" void kernel_launch(void* const* d_in, const int* in_sizes, int n_in,
                              void* d_out, int out_size) {
    const float* x   = (const float*)d_in[0];
    const int*   ei  = (const int*)d_in[1];     // int32 (JAX x64 disabled)
    const float* W1  = (const float*)d_in[2];
    const float* b1  = (const float*)d_in[3];
    const float* W2  = (const float*)d_in[4];
    const float* b2  = (const float*)d_in[5];
    const float* cls = (const float*)d_in[6];
    float* out = (float*)d_out;

    const int E = in_sizes[1] / 2;
    const int* erow = ei;
    const int* ecol = ei + E;

    // CSR build (once, reused for both layers)
    k_cnt_init<<<(N_NODES + 255) / 256, 256>>>();
    k_deg_count<<<(E + 255) / 256, 256>>>(ecol, E);
    k_dinv<<<(N_NODES + 255) / 256, 256>>>();
    k_scan1<<<NB_SCAN, 512>>>();
    k_scan2<<<1, 256>>>();
    k_scan3<<<NB_SCAN, 512>>>();
    k_bucket<<<(E + 255) / 256, 256>>>(erow, ecol, E);
    k_clsnorm<<<C_CLS, 128>>>(cls);

    // Layer 1
    k_gemm1<<<N_NODES / 32, 128>>>(x, W1);
    k_aggregate<<<(N_NODES * 32 + 255) / 256, 256>>>();
    // Layer 2
    k_gemm2<<<N_NODES / 32, 128>>>(W2, b1);
    k_aggregate<<<(N_NODES * 32 + 255) / 256, 256>>>();
    // Head
    k_final<<<(N_NODES + 127) / 128, 128>>>(b2, out);
}

// round 6
// speedup vs baseline: 2.5506x; 1.0449x over previous
#include <cuda_runtime.h>

#define N_NODES 100000
#define E_MAX   1600000
#define D_IN    256
#define D_H     128
#define C_CLS   40
#define NB_SCAN ((N_NODES + 511) / 512)   // 196

typedef unsigned long long u64;

// ---- packed f32x2 helpers (Blackwell FFMA2 path, PTX-only) ----
__device__ __forceinline__ u64 f2pk(float lo, float hi) {
    u64 r; asm("mov.b64 %0, {%1, %2};" : "=l"(r) : "f"(lo), "f"(hi)); return r;
}
__device__ __forceinline__ u64 f2dup(float a) {
    u64 r; asm("mov.b64 %0, {%1, %1};" : "=l"(r) : "f"(a)); return r;
}
__device__ __forceinline__ void f2fma(u64& d, u64 a, u64 b) {
    asm("fma.rn.f32x2 %0, %1, %2, %0;" : "+l"(d) : "l"(a), "l"(b));
}
__device__ __forceinline__ float2 f2upk(u64 v) {
    float2 f; asm("mov.b64 {%0, %1}, %2;" : "=f"(f.x), "=f"(f.y) : "l"(v)); return f;
}

// ---- scratch ----
__device__ int   g_cnt[N_NODES];
__device__ int   g_start[N_NODES];
__device__ int   g_head[N_NODES];
__device__ int   g_partial[NB_SCAN];
__device__ int   g_csr_src[E_MAX];
__device__ float g_dinv[N_NODES];
__device__ float g_A[(size_t)N_NODES * D_H];
__device__ float g_B[(size_t)N_NODES * D_H];
__device__ float g_clsn[C_CLS * D_H];

// ---------------------------------------------------------------------------
__global__ void k_cnt_init() {
    int i = blockIdx.x * blockDim.x + threadIdx.x;
    if (i < N_NODES) g_cnt[i] = 0;
}

__global__ void k_deg_count(const int* __restrict__ col, int E) {
    int e = blockIdx.x * blockDim.x + threadIdx.x;
    if (e < E) atomicAdd(&g_cnt[col[e]], 1);
}

__global__ void k_dinv() {
    int i = blockIdx.x * blockDim.x + threadIdx.x;
    if (i < N_NODES) g_dinv[i] = rsqrtf((float)(g_cnt[i] + 1));
}

// ---- two-level exclusive scan ----
__global__ void k_scan1() {
    __shared__ int s[512];
    int i = blockIdx.x * 512 + threadIdx.x;
    s[threadIdx.x] = (i < N_NODES) ? g_cnt[i] : 0;
    __syncthreads();
    for (int off = 256; off > 0; off >>= 1) {
        if (threadIdx.x < off) s[threadIdx.x] += s[threadIdx.x + off];
        __syncthreads();
    }
    if (threadIdx.x == 0) g_partial[blockIdx.x] = s[0];
}

__global__ void k_scan2() {
    __shared__ int s[256];
    int t = threadIdx.x;
    s[t] = (t < NB_SCAN) ? g_partial[t] : 0;
    __syncthreads();
    for (int off = 1; off < 256; off <<= 1) {
        int v = (t >= off) ? s[t - off] : 0;
        __syncthreads();
        s[t] += v;
        __syncthreads();
    }
    if (t < NB_SCAN) g_partial[t] = s[t] - ((t < NB_SCAN) ? g_partial[t] : 0);
}

__global__ void k_scan3() {
    __shared__ int s[512];
    int t = threadIdx.x;
    int i = blockIdx.x * 512 + t;
    int own = (i < N_NODES) ? g_cnt[i] : 0;
    s[t] = own;
    __syncthreads();
    for (int off = 1; off < 512; off <<= 1) {
        int v = (t >= off) ? s[t - off] : 0;
        __syncthreads();
        s[t] += v;
        __syncthreads();
    }
    if (i < N_NODES) {
        int st = s[t] - own + g_partial[blockIdx.x];
        g_start[i] = st;
        g_head[i]  = st;
    }
}

__global__ void k_bucket(const int* __restrict__ row, const int* __restrict__ col, int E) {
    int e = blockIdx.x * blockDim.x + threadIdx.x;
    if (e < E) {
        int pos = atomicAdd(&g_head[col[e]], 1);
        g_csr_src[pos] = row[e];
    }
}

// ---------------------------------------------------------------------------
// GEMM1 (packed FFMA2): A[i][c] = dinv[i] * sum_k x[i][k] * W1[k][c]
__global__ void k_gemm1(const float* __restrict__ x, const float* __restrict__ W1) {
    __shared__ float4 xs4[32 * 64];
    const int t = threadIdx.x;
    const int row0 = blockIdx.x * 32;
    const float4* xv = (const float4*)x;
    for (int idx = t; idx < 32 * 64; idx += 128)
        xs4[idx] = xv[(size_t)row0 * 64 + idx];
    __syncthreads();

    const int lane = t & 31;
    const int w = t >> 5;
    u64 a01[8], a23[8];
#pragma unroll
    for (int r = 0; r < 8; r++) { a01[r] = 0ull; a23[r] = 0ull; }

    const float4* W1v = (const float4*)W1;
    for (int k = 0; k < D_IN; k += 4) {
        float4 w0 = W1v[(k + 0) * 32 + lane];
        float4 w1 = W1v[(k + 1) * 32 + lane];
        float4 w2 = W1v[(k + 2) * 32 + lane];
        float4 w3 = W1v[(k + 3) * 32 + lane];
        u64 w0lo = f2pk(w0.x, w0.y), w0hi = f2pk(w0.z, w0.w);
        u64 w1lo = f2pk(w1.x, w1.y), w1hi = f2pk(w1.z, w1.w);
        u64 w2lo = f2pk(w2.x, w2.y), w2hi = f2pk(w2.z, w2.w);
        u64 w3lo = f2pk(w3.x, w3.y), w3hi = f2pk(w3.z, w3.w);
#pragma unroll
        for (int r = 0; r < 8; r++) {
            float4 xq = xs4[(w * 8 + r) * 64 + (k >> 2)];
            u64 dx;
            dx = f2dup(xq.x); f2fma(a01[r], dx, w0lo); f2fma(a23[r], dx, w0hi);
            dx = f2dup(xq.y); f2fma(a01[r], dx, w1lo); f2fma(a23[r], dx, w1hi);
            dx = f2dup(xq.z); f2fma(a01[r], dx, w2lo); f2fma(a23[r], dx, w2hi);
            dx = f2dup(xq.w); f2fma(a01[r], dx, w3lo); f2fma(a23[r], dx, w3hi);
        }
    }

#pragma unroll
    for (int r = 0; r < 8; r++) {
        int row = row0 + w * 8 + r;
        float s = g_dinv[row];
        float2 p = f2upk(a01[r]);
        float2 q = f2upk(a23[r]);
        ((float4*)g_A)[(size_t)row * 32 + lane] =
            make_float4(p.x * s, p.y * s, q.x * s, q.y * s);
    }
}

// ---------------------------------------------------------------------------
// Aggregate (CSR gather): B[j] = A[j] + sum_{src in csr[j]} A[src]. Warp/node.
__global__ void k_aggregate() {
    int node = (int)((blockIdx.x * (long long)blockDim.x + threadIdx.x) >> 5);
    int lane = threadIdx.x & 31;
    if (node >= N_NODES) return;
    const float4* Av = (const float4*)g_A;
    float4 a = Av[(size_t)node * 32 + lane];
    float acc0 = a.x, acc1 = a.y, acc2 = a.z, acc3 = a.w;
    int s = g_start[node];
    int c = g_cnt[node];
    int k = 0;
    for (; k + 4 <= c; k += 4) {
        int s0 = g_csr_src[s + k + 0];
        int s1 = g_csr_src[s + k + 1];
        int s2 = g_csr_src[s + k + 2];
        int s3 = g_csr_src[s + k + 3];
        float4 v0 = Av[(size_t)s0 * 32 + lane];
        float4 v1 = Av[(size_t)s1 * 32 + lane];
        float4 v2 = Av[(size_t)s2 * 32 + lane];
        float4 v3 = Av[(size_t)s3 * 32 + lane];
        acc0 += v0.x + v1.x + v2.x + v3.x;
        acc1 += v0.y + v1.y + v2.y + v3.y;
        acc2 += v0.z + v1.z + v2.z + v3.z;
        acc3 += v0.w + v1.w + v2.w + v3.w;
    }
    for (; k < c; k++) {
        int s0 = g_csr_src[s + k];
        float4 v0 = Av[(size_t)s0 * 32 + lane];
        acc0 += v0.x; acc1 += v0.y; acc2 += v0.z; acc3 += v0.w;
    }
    ((float4*)g_B)[(size_t)node * 32 + lane] = make_float4(acc0, acc1, acc2, acc3);
}

// ---------------------------------------------------------------------------
// GEMM2 (packed FFMA2): h = relu(dinv*B + b1); A = dinv * (h @ W2)
__global__ void k_gemm2(const float* __restrict__ W2, const float* __restrict__ b1) {
    __shared__ float4 hs4[32 * 32];
    __shared__ float  sdinv[32];
    __shared__ float4 sb1[32];
    const int t = threadIdx.x;
    const int row0 = blockIdx.x * 32;
    if (t < 32) { sdinv[t] = g_dinv[row0 + t]; sb1[t] = ((const float4*)b1)[t]; }
    __syncthreads();

    for (int idx = t; idx < 32 * 32; idx += 128) {
        int rr = idx >> 5, cc = idx & 31;
        float4 v = ((const float4*)g_B)[(size_t)row0 * 32 + idx];
        float s = sdinv[rr];
        float4 bb = sb1[cc];
        float4 h;
        h.x = fmaxf(fmaf(s, v.x, bb.x), 0.f);
        h.y = fmaxf(fmaf(s, v.y, bb.y), 0.f);
        h.z = fmaxf(fmaf(s, v.z, bb.z), 0.f);
        h.w = fmaxf(fmaf(s, v.w, bb.w), 0.f);
        hs4[idx] = h;
    }
    __syncthreads();

    const int lane = t & 31;
    const int w = t >> 5;
    u64 a01[8], a23[8];
#pragma unroll
    for (int r = 0; r < 8; r++) { a01[r] = 0ull; a23[r] = 0ull; }

    const float4* W2v = (const float4*)W2;
    for (int k = 0; k < D_H; k += 4) {
        float4 w0 = W2v[(k + 0) * 32 + lane];
        float4 w1 = W2v[(k + 1) * 32 + lane];
        float4 w2 = W2v[(k + 2) * 32 + lane];
        float4 w3 = W2v[(k + 3) * 32 + lane];
        u64 w0lo = f2pk(w0.x, w0.y), w0hi = f2pk(w0.z, w0.w);
        u64 w1lo = f2pk(w1.x, w1.y), w1hi = f2pk(w1.z, w1.w);
        u64 w2lo = f2pk(w2.x, w2.y), w2hi = f2pk(w2.z, w2.w);
        u64 w3lo = f2pk(w3.x, w3.y), w3hi = f2pk(w3.z, w3.w);
#pragma unroll
        for (int r = 0; r < 8; r++) {
            float4 xq = hs4[(w * 8 + r) * 32 + (k >> 2)];
            u64 dx;
            dx = f2dup(xq.x); f2fma(a01[r], dx, w0lo); f2fma(a23[r], dx, w0hi);
            dx = f2dup(xq.y); f2fma(a01[r], dx, w1lo); f2fma(a23[r], dx, w1hi);
            dx = f2dup(xq.z); f2fma(a01[r], dx, w2lo); f2fma(a23[r], dx, w2hi);
            dx = f2dup(xq.w); f2fma(a01[r], dx, w3lo); f2fma(a23[r], dx, w3hi);
        }
    }

#pragma unroll
    for (int r = 0; r < 8; r++) {
        int row = row0 + w * 8 + r;
        float s = sdinv[w * 8 + r];
        float2 p = f2upk(a01[r]);
        float2 q = f2upk(a23[r]);
        ((float4*)g_A)[(size_t)row * 32 + lane] =
            make_float4(p.x * s, p.y * s, q.x * s, q.y * s);
    }
}

// ---------------------------------------------------------------------------
__global__ void k_clsnorm(const float* __restrict__ cls) {
    int c = blockIdx.x, t = threadIdx.x;
    float v = cls[c * D_H + t];
    float s = v * v;
#pragma unroll
    for (int o = 16; o; o >>= 1) s += __shfl_xor_sync(0xffffffffu, s, o);
    __shared__ float ws[4];
    if ((t & 31) == 0) ws[t >> 5] = s;
    __syncthreads();
    float tot = ws[0] + ws[1] + ws[2] + ws[3];
    float inv = 1.f / fmaxf(sqrtf(tot), 1e-8f);
    g_clsn[c * D_H + t] = v * inv;
}

// Final (packed FFMA2): h2 = dinv*B + b2; out = (h2 . clsn[c]) / max(||h2||,eps)
__global__ void k_final(const float* __restrict__ b2, float* __restrict__ out) {
    __shared__ float4 scls[C_CLS * 32];
    __shared__ float4 sb2[32];
    const int t = threadIdx.x;
    for (int idx = t; idx < C_CLS * 32; idx += 128)
        scls[idx] = ((const float4*)g_clsn)[idx];
    if (t < 32) sb2[t] = ((const float4*)b2)[t];
    __syncthreads();

    int i = blockIdx.x * 128 + t;
    if (i >= N_NODES) return;
    u64 acc2[C_CLS];
#pragma unroll
    for (int c = 0; c < C_CLS; c++) acc2[c] = 0ull;
    u64 sq01 = 0ull, sq23 = 0ull;
    float s = g_dinv[i];
    const float4* Bp = (const float4*)g_B;
    for (int kq = 0; kq < 32; kq++) {
        float4 v = Bp[(size_t)i * 32 + kq];
        float4 bb = sb2[kq];
        float4 h;
        h.x = fmaf(s, v.x, bb.x);
        h.y = fmaf(s, v.y, bb.y);
        h.z = fmaf(s, v.z, bb.z);
        h.w = fmaf(s, v.w, bb.w);
        u64 h01 = f2pk(h.x, h.y), h23 = f2pk(h.z, h.w);
        f2fma(sq01, h01, h01);
        f2fma(sq23, h23, h23);
#pragma unroll
        for (int c = 0; c < C_CLS; c++) {
            float4 cv = scls[c * 32 + kq];
            f2fma(acc2[c], h01, f2pk(cv.x, cv.y));
            f2fma(acc2[c], h23, f2pk(cv.z, cv.w));
        }
    }
    float2 e0 = f2upk(sq01), e1 = f2upk(sq23);
    float sumsq = (e0.x + e0.y) + (e1.x + e1.y);
    float inv = 1.f / fmaxf(sqrtf(sumsq), 1e-8f);
#pragma unroll
    for (int c = 0; c < C_CLS; c++) {
        float2 p = f2upk(acc2[c]);
        out[(size_t)i * C_CLS + c] = (p.x + p.y) * inv;
    }
}

// ---------------------------------------------------------------------------
extern "C" void kernel_launch(void* const* d_in, const int* in_sizes, int n_in,
                              void* d_out, int out_size) {
    const float* x   = (const float*)d_in[0];
    const int*   ei  = (const int*)d_in[1];     // int32 (JAX x64 disabled)
    const float* W1  = (const float*)d_in[2];
    const float* b1  = (const float*)d_in[3];
    const float* W2  = (const float*)d_in[4];
    const float* b2  = (const float*)d_in[5];
    const float* cls = (const float*)d_in[6];
    float* out = (float*)d_out;

    const int E = in_sizes[1] / 2;
    const int* erow = ei;
    const int* ecol = ei + E;

    // CSR build (once, reused for both layers)
    k_cnt_init<<<(N_NODES + 255) / 256, 256>>>();
    k_deg_count<<<(E + 255) / 256, 256>>>(ecol, E);
    k_dinv<<<(N_NODES + 255) / 256, 256>>>();
    k_scan1<<<NB_SCAN, 512>>>();
    k_scan2<<<1, 256>>>();
    k_scan3<<<NB_SCAN, 512>>>();
    k_bucket<<<(E + 255) / 256, 256>>>(erow, ecol, E);
    k_clsnorm<<<C_CLS, 128>>>(cls);

    // Layer 1
    k_gemm1<<<N_NODES / 32, 128>>>(x, W1);
    k_aggregate<<<(N_NODES * 32 + 255) / 256, 256>>>();
    // Layer 2
    k_gemm2<<<N_NODES / 32, 128>>>(W2, b1);
    k_aggregate<<<(N_NODES * 32 + 255) / 256, 256>>>();
    // Head
    k_final<<<(N_NODES + 127) / 128, 128>>>(b2, out);
}